// round 3
// baseline (speedup 1.0000x reference)
#include <cuda_runtime.h>

#define HIDDEN    2048
#define NUM_HEADS 16
#define HEAD_DIM  128
#define BLK_SZ    64
#define NUM_SEQS  64
#define MAX_BLK   32
#define KS        4
#define ATTN_SCALE 0.08838834764831845f   // 128^-0.5

// scratch (allocation-free: __device__ globals), 16B-aligned for float4 access
__device__ __align__(16) float g_q[NUM_SEQS * HIDDEN];
__device__ __align__(16) float g_attn[NUM_SEQS * HIDDEN];
__device__ __align__(16) float g_part[KS * NUM_SEQS * HIDDEN];

// ---------------------------------------------------------------------------
// Split-K tiled GEMM: C_part[z] = A[64, 0:512@z] * B[0:512@z, n0:n0+64]
// M=64, N=2048, K=2048. BM=64, BN=64, BK=16. 256 thr, 4x4 micro-tile.
// grid = (32, 1, 4)
// ---------------------------------------------------------------------------
__global__ void gemm_part(const float* __restrict__ A, const float* __restrict__ B,
                          float* __restrict__ C, int ldb) {
    __shared__ __align__(16) float As[16 * 68];   // [k][m], padded stride 68
    __shared__ __align__(16) float Bs[16 * 64];   // [k][n]

    const int tid = threadIdx.x;
    const int tm  = tid >> 4;       // 0..15
    const int tn  = tid & 15;       // 0..15
    const int n0  = blockIdx.x * 64;
    const int z   = blockIdx.z;

    // load mappings
    const int am  = tid >> 2;         // A row 0..63
    const int akq = (tid & 3) * 4;    // A k-offset {0,4,8,12}
    const int bk  = tid >> 4;         // B k 0..15
    const int bnq = (tid & 15) * 4;   // B n-offset

    float acc[4][4] = {};

    for (int it = 0; it < 32; ++it) {
        const int k0 = z * 512 + it * 16;

        float4 a4 = *(const float4*)(A + (size_t)am * HIDDEN + k0 + akq);
        As[(akq + 0) * 68 + am] = a4.x;
        As[(akq + 1) * 68 + am] = a4.y;
        As[(akq + 2) * 68 + am] = a4.z;
        As[(akq + 3) * 68 + am] = a4.w;

        float4 b4 = *(const float4*)(B + (size_t)(k0 + bk) * ldb + n0 + bnq);
        *(float4*)(Bs + bk * 64 + bnq) = b4;

        __syncthreads();
#pragma unroll
        for (int kk = 0; kk < 16; ++kk) {
            float4 av = *(const float4*)(As + kk * 68 + tm * 4);
            float4 bv = *(const float4*)(Bs + kk * 64 + tn * 4);
            float aa[4] = {av.x, av.y, av.z, av.w};
            float bb[4] = {bv.x, bv.y, bv.z, bv.w};
#pragma unroll
            for (int i = 0; i < 4; ++i)
#pragma unroll
                for (int j = 0; j < 4; ++j)
                    acc[i][j] += aa[i] * bb[j];
        }
        __syncthreads();
    }

#pragma unroll
    for (int i = 0; i < 4; ++i) {
        float4 v = make_float4(acc[i][0], acc[i][1], acc[i][2], acc[i][3]);
        *(float4*)(C + ((size_t)z * 64 + tm * 4 + i) * HIDDEN + n0 + tn * 4) = v;
    }
}

// out[i] = sum_z part[z][i] + bias[i % 2048]  (float4-vectorized)
__global__ void reduce_bias(const float* __restrict__ part,
                            const float* __restrict__ bias,
                            float* __restrict__ out) {
    const int i = blockIdx.x * blockDim.x + threadIdx.x;   // 0..32767 (float4 idx)
    const float4* p = (const float4*)part;
    float4 a = p[i];
    float4 b = p[i + 32768];
    float4 c = p[i + 65536];
    float4 d = p[i + 98304];
    float4 bi = ((const float4*)bias)[i & 511];
    float4 r;
    r.x = a.x + b.x + c.x + d.x + bi.x;
    r.y = a.y + b.y + c.y + d.y + bi.y;
    r.z = a.z + b.z + c.z + d.z + bi.z;
    r.w = a.w + b.w + c.w + d.w + bi.w;
    ((float4*)out)[i] = r;
}

// ---------------------------------------------------------------------------
// Paged decode attention. grid = (64 seqs, 16 heads), 256 threads.
// Pass 1: warp-per-token q.k dots (coalesced 512B/token).
// Softmax in SMEM. Pass 2: warp-per-token weighted V accumulate.
// ---------------------------------------------------------------------------
__global__ void attn_kernel(const float* __restrict__ kv,
                            const int* __restrict__ bt,
                            const int* __restrict__ seq_lens) {
    const int s = blockIdx.x, h = blockIdx.y;
    const int tid = threadIdx.x;
    const int w = tid >> 5, l = tid & 31;

    __shared__ __align__(16) float qs[HEAD_DIM];
    __shared__ __align__(16) float vacc[8][HEAD_DIM];
    __shared__ float sc[2048];
    __shared__ int   bts[MAX_BLK];
    __shared__ float red[8];
    __shared__ float bcast[2];

    if (tid < HEAD_DIM) qs[tid] = g_q[(size_t)s * HIDDEN + h * HEAD_DIM + tid];
    if (tid < MAX_BLK)  bts[tid] = bt[s * MAX_BLK + tid];
    const int sl = seq_lens[s];
    __syncthreads();

    const float4 qreg = *(const float4*)(qs + l * 4);
    const float* kbase = kv + (size_t)h * HEAD_DIM;

    // pass 1: scores
    for (int t = w; t < sl; t += 8) {
        const int phys = bts[t >> 6];
        const float4* kp = (const float4*)(kbase +
            (size_t)(phys * BLK_SZ + (t & 63)) * (NUM_HEADS * HEAD_DIM)) + l;
        float4 kf = *kp;
        float d = qreg.x * kf.x + qreg.y * kf.y + qreg.z * kf.z + qreg.w * kf.w;
        d += __shfl_xor_sync(0xffffffffu, d, 16);
        d += __shfl_xor_sync(0xffffffffu, d, 8);
        d += __shfl_xor_sync(0xffffffffu, d, 4);
        d += __shfl_xor_sync(0xffffffffu, d, 2);
        d += __shfl_xor_sync(0xffffffffu, d, 1);
        if (l == 0) sc[t] = d * ATTN_SCALE;
    }
    __syncthreads();

    // max
    float m = -3.4e38f;
    for (int t = tid; t < sl; t += 256) m = fmaxf(m, sc[t]);
#pragma unroll
    for (int o = 16; o; o >>= 1) m = fmaxf(m, __shfl_xor_sync(0xffffffffu, m, o));
    if (l == 0) red[w] = m;
    __syncthreads();
    if (tid == 0) {
        float mm = red[0];
#pragma unroll
        for (int i = 1; i < 8; ++i) mm = fmaxf(mm, red[i]);
        bcast[0] = mm;
    }
    __syncthreads();
    const float maxv = bcast[0];

    // exp + sum
    float ssum = 0.f;
    for (int t = tid; t < sl; t += 256) {
        float e = __expf(sc[t] - maxv);
        sc[t] = e;
        ssum += e;
    }
#pragma unroll
    for (int o = 16; o; o >>= 1) ssum += __shfl_xor_sync(0xffffffffu, ssum, o);
    if (l == 0) red[w] = ssum;
    __syncthreads();
    if (tid == 0) {
        float t2 = 0.f;
#pragma unroll
        for (int i = 0; i < 8; ++i) t2 += red[i];
        bcast[1] = 1.f / t2;
    }
    __syncthreads();

    // pass 2: weighted V
    const float* vbase = kv + (size_t)2048 * 64 * 16 * 128 + (size_t)h * HEAD_DIM;
    float4 acc = make_float4(0.f, 0.f, 0.f, 0.f);
    for (int t = w; t < sl; t += 8) {
        const int phys = bts[t >> 6];
        const float4* vp = (const float4*)(vbase +
            (size_t)(phys * BLK_SZ + (t & 63)) * (NUM_HEADS * HEAD_DIM)) + l;
        float4 vf = *vp;
        const float wt = sc[t];
        acc.x += wt * vf.x;
        acc.y += wt * vf.y;
        acc.z += wt * vf.z;
        acc.w += wt * vf.w;
    }
    *(float4*)(&vacc[w][l * 4]) = acc;
    __syncthreads();

    if (tid < HEAD_DIM) {
        float r = 0.f;
#pragma unroll
        for (int ww = 0; ww < 8; ++ww) r += vacc[ww][tid];
        g_attn[(size_t)s * HIDDEN + h * HEAD_DIM + tid] = r * bcast[1];
    }
}

// ---------------------------------------------------------------------------
extern "C" void kernel_launch(void* const* d_in, const int* in_sizes, int n_in,
                              void* d_out, int out_size) {
    const float* hs     = (const float*)d_in[0];
    const float* kv     = (const float*)d_in[1];
    const float* W_attn = (const float*)d_in[2];
    const float* b_attn = (const float*)d_in[3];
    const float* W_proj = (const float*)d_in[4];
    const float* b_proj = (const float*)d_in[5];
    const int*   bt     = (const int*)d_in[6];
    const int*   sl     = (const int*)d_in[7];
    float* out = (float*)d_out;

    float *q_ptr, *attn_ptr, *part_ptr;
    cudaGetSymbolAddress((void**)&q_ptr,    g_q);
    cudaGetSymbolAddress((void**)&attn_ptr, g_attn);
    cudaGetSymbolAddress((void**)&part_ptr, g_part);

    // Q projection only: reference never uses K/V columns of W_attn.
    gemm_part<<<dim3(32, 1, KS), 256>>>(hs, W_attn, part_ptr, 3 * HIDDEN);
    reduce_bias<<<128, 256>>>(part_ptr, b_attn, q_ptr);

    attn_kernel<<<dim3(NUM_SEQS, NUM_HEADS), 256>>>(kv, bt, sl);

    gemm_part<<<dim3(32, 1, KS), 256>>>(attn_ptr, W_proj, part_ptr, HIDDEN);
    reduce_bias<<<128, 256>>>(part_ptr, b_proj, out);
}

// round 4
// speedup vs baseline: 1.3621x; 1.3621x over previous
#include <cuda_runtime.h>

#define HIDDEN    2048
#define NUM_HEADS 16
#define HEAD_DIM  128
#define BLK_SZ    64
#define NUM_SEQS  64
#define MAX_BLK   32
#define KS        16
#define ATTN_SCALE 0.08838834764831845f   // 128^-0.5

// scratch (allocation-free __device__ globals), 16B-aligned for float4 access
__device__ __align__(16) float g_q[NUM_SEQS * HIDDEN];
__device__ __align__(16) float g_attn[NUM_SEQS * HIDDEN];
__device__ __align__(16) float g_part[KS * NUM_SEQS * HIDDEN];   // 8 MB

// ---------------------------------------------------------------------------
// Split-K tiled GEMM: C_part[z] = A[64, z*128:(z+1)*128] * B[..., n0:n0+64]
// BM=64, BN=64, BK=16, 8 K-tiles per CTA, double-buffered SMEM.
// grid = (32, 1, 16) = 512 CTAs (~3.5/SM), 256 threads, 4x4 micro-tile.
// ---------------------------------------------------------------------------
__global__ void gemm_part(const float* __restrict__ A, const float* __restrict__ B,
                          float* __restrict__ C, int ldb) {
    __shared__ __align__(16) float As[2][16 * 68];
    __shared__ __align__(16) float Bs[2][16 * 64];

    const int tid = threadIdx.x;
    const int tm  = tid >> 4;
    const int tn  = tid & 15;
    const int n0  = blockIdx.x * 64;
    const int z   = blockIdx.z;

    const int am  = tid >> 2;         // A row 0..63
    const int akq = (tid & 3) * 4;    // A k-offset {0,4,8,12}
    const int bk  = tid >> 4;         // B k 0..15
    const int bnq = (tid & 15) * 4;   // B n-offset

    const int kbase = z * 128;

    // prologue: stage 0
    {
        float4 a4 = *(const float4*)(A + (size_t)am * HIDDEN + kbase + akq);
        As[0][(akq + 0) * 68 + am] = a4.x;
        As[0][(akq + 1) * 68 + am] = a4.y;
        As[0][(akq + 2) * 68 + am] = a4.z;
        As[0][(akq + 3) * 68 + am] = a4.w;
        float4 b4 = *(const float4*)(B + (size_t)(kbase + bk) * ldb + n0 + bnq);
        *(float4*)(&Bs[0][bk * 64 + bnq]) = b4;
    }
    __syncthreads();

    float acc[4][4] = {};

#pragma unroll
    for (int it = 0; it < 8; ++it) {
        const int cur = it & 1;
        float4 a4, b4;
        if (it < 7) {
            const int k0 = kbase + (it + 1) * 16;
            a4 = *(const float4*)(A + (size_t)am * HIDDEN + k0 + akq);
            b4 = *(const float4*)(B + (size_t)(k0 + bk) * ldb + n0 + bnq);
        }
#pragma unroll
        for (int kk = 0; kk < 16; ++kk) {
            float4 av = *(const float4*)(&As[cur][kk * 68 + tm * 4]);
            float4 bv = *(const float4*)(&Bs[cur][kk * 64 + tn * 4]);
            float aa[4] = {av.x, av.y, av.z, av.w};
            float bb[4] = {bv.x, bv.y, bv.z, bv.w};
#pragma unroll
            for (int i = 0; i < 4; ++i)
#pragma unroll
                for (int j = 0; j < 4; ++j)
                    acc[i][j] += aa[i] * bb[j];
        }
        if (it < 7) {
            const int nxt = 1 - cur;
            As[nxt][(akq + 0) * 68 + am] = a4.x;
            As[nxt][(akq + 1) * 68 + am] = a4.y;
            As[nxt][(akq + 2) * 68 + am] = a4.z;
            As[nxt][(akq + 3) * 68 + am] = a4.w;
            *(float4*)(&Bs[nxt][bk * 64 + bnq]) = b4;
        }
        __syncthreads();
    }

#pragma unroll
    for (int i = 0; i < 4; ++i) {
        float4 v = make_float4(acc[i][0], acc[i][1], acc[i][2], acc[i][3]);
        *(float4*)(C + ((size_t)z * 64 + tm * 4 + i) * HIDDEN + n0 + tn * 4) = v;
    }
}

// out[i] = sum_z part[z][i] + bias[i % 2048]  (float4)
__global__ void reduce_bias(const float* __restrict__ part,
                            const float* __restrict__ bias,
                            float* __restrict__ out) {
    const int i = blockIdx.x * blockDim.x + threadIdx.x;   // 0..32767
    const float4* p = (const float4*)part;
    float4 r = ((const float4*)bias)[i & 511];
#pragma unroll
    for (int zz = 0; zz < KS; ++zz) {
        float4 a = p[i + zz * 32768];
        r.x += a.x; r.y += a.y; r.z += a.z; r.w += a.w;
    }
    ((float4*)out)[i] = r;
}

// ---------------------------------------------------------------------------
// Paged decode attention. grid = (64 seqs, 16 heads), 256 threads (8 warps).
// Token-per-quad layout: 4 lanes per token, 8 tokens per warp per round,
// 64 tokens (one KV block) per CTA round. MLP=8 loads/warp-iter, 2 shuffles
// reduce all 8 token dots at once.
// ---------------------------------------------------------------------------
__global__ void attn_kernel(const float* __restrict__ kv,
                            const int* __restrict__ bt,
                            const int* __restrict__ seq_lens) {
    const int s = blockIdx.x, h = blockIdx.y;
    const int tid = threadIdx.x;
    const int w  = tid >> 5;
    const int l  = tid & 31;
    const int q4 = l & 3;     // lane within quad (dim slice)
    const int qd = l >> 2;    // quad id -> token within warp's 8

    __shared__ __align__(16) float qs[HEAD_DIM];
    __shared__ __align__(16) float vacc[8][HEAD_DIM];
    __shared__ float sc[2048];
    __shared__ int   bts[MAX_BLK];
    __shared__ float red[8];
    __shared__ float bcast[2];

    if (tid < HEAD_DIM) qs[tid] = g_q[(size_t)s * HIDDEN + h * HEAD_DIM + tid];
    if (tid < MAX_BLK)  bts[tid] = bt[s * MAX_BLK + tid];
    const int sl = seq_lens[s];
    __syncthreads();

    // per-lane q slices: dims c*16 + q4*4 .. +4, c = 0..7
    float4 qreg[8];
#pragma unroll
    for (int c = 0; c < 8; ++c) qreg[c] = *(const float4*)(qs + c * 16 + q4 * 4);

    const int nblk = (sl + 63) >> 6;
    const int tok_in_blk = w * 8 + qd;           // 0..63
    const float* kbase = kv + (size_t)h * HEAD_DIM;

    // ---- pass 1: scores ----
    for (int blk = 0; blk < nblk; ++blk) {
        const int phys = bts[blk];
        const int t = blk * 64 + tok_in_blk;
        const float* kp = kbase + ((size_t)phys * BLK_SZ + tok_in_blk) * (size_t)HIDDEN;
        float d = 0.f;
#pragma unroll
        for (int c = 0; c < 8; ++c) {
            float4 kf = *(const float4*)(kp + c * 16 + q4 * 4);
            d += qreg[c].x * kf.x + qreg[c].y * kf.y + qreg[c].z * kf.z + qreg[c].w * kf.w;
        }
        d += __shfl_xor_sync(0xffffffffu, d, 1);
        d += __shfl_xor_sync(0xffffffffu, d, 2);
        if (q4 == 0 && t < sl) sc[t] = d * ATTN_SCALE;
    }
    __syncthreads();

    // ---- softmax: max ----
    float m = -3.4e38f;
    for (int t = tid; t < sl; t += 256) m = fmaxf(m, sc[t]);
#pragma unroll
    for (int o = 16; o; o >>= 1) m = fmaxf(m, __shfl_xor_sync(0xffffffffu, m, o));
    if (l == 0) red[w] = m;
    __syncthreads();
    if (tid == 0) {
        float mm = red[0];
#pragma unroll
        for (int i = 1; i < 8; ++i) mm = fmaxf(mm, red[i]);
        bcast[0] = mm;
    }
    __syncthreads();
    const float maxv = bcast[0];

    // ---- softmax: exp + sum ----
    float ssum = 0.f;
    for (int t = tid; t < sl; t += 256) {
        float e = __expf(sc[t] - maxv);
        sc[t] = e;
        ssum += e;
    }
#pragma unroll
    for (int o = 16; o; o >>= 1) ssum += __shfl_xor_sync(0xffffffffu, ssum, o);
    if (l == 0) red[w] = ssum;
    __syncthreads();
    if (tid == 0) {
        float t2 = 0.f;
#pragma unroll
        for (int i = 0; i < 8; ++i) t2 += red[i];
        bcast[1] = 1.f / t2;
    }
    __syncthreads();

    // ---- pass 2: weighted V ----
    const float* vbase = kv + (size_t)2048 * 64 * 16 * 128 + (size_t)h * HEAD_DIM;
    float4 acc[8];
#pragma unroll
    for (int c = 0; c < 8; ++c) acc[c] = make_float4(0.f, 0.f, 0.f, 0.f);

    for (int blk = 0; blk < nblk; ++blk) {
        const int phys = bts[blk];
        const int t = blk * 64 + tok_in_blk;
        const float wt = (t < sl) ? sc[t] : 0.f;
        const float* vp = vbase + ((size_t)phys * BLK_SZ + tok_in_blk) * (size_t)HIDDEN;
#pragma unroll
        for (int c = 0; c < 8; ++c) {
            float4 vf = *(const float4*)(vp + c * 16 + q4 * 4);
            acc[c].x += wt * vf.x;
            acc[c].y += wt * vf.y;
            acc[c].z += wt * vf.z;
            acc[c].w += wt * vf.w;
        }
    }

    // cross-quad reduction (quads hold different token subsets, same dims)
#pragma unroll
    for (int off = 4; off <= 16; off <<= 1) {
#pragma unroll
        for (int c = 0; c < 8; ++c) {
            acc[c].x += __shfl_xor_sync(0xffffffffu, acc[c].x, off);
            acc[c].y += __shfl_xor_sync(0xffffffffu, acc[c].y, off);
            acc[c].z += __shfl_xor_sync(0xffffffffu, acc[c].z, off);
            acc[c].w += __shfl_xor_sync(0xffffffffu, acc[c].w, off);
        }
    }
    if (qd == 0) {
#pragma unroll
        for (int c = 0; c < 8; ++c)
            *(float4*)(&vacc[w][c * 16 + q4 * 4]) = acc[c];
    }
    __syncthreads();

    if (tid < HEAD_DIM) {
        float r = 0.f;
#pragma unroll
        for (int ww = 0; ww < 8; ++ww) r += vacc[ww][tid];
        g_attn[(size_t)s * HIDDEN + h * HEAD_DIM + tid] = r * bcast[1];
    }
}

// ---------------------------------------------------------------------------
extern "C" void kernel_launch(void* const* d_in, const int* in_sizes, int n_in,
                              void* d_out, int out_size) {
    const float* hs     = (const float*)d_in[0];
    const float* kv     = (const float*)d_in[1];
    const float* W_attn = (const float*)d_in[2];
    const float* b_attn = (const float*)d_in[3];
    const float* W_proj = (const float*)d_in[4];
    const float* b_proj = (const float*)d_in[5];
    const int*   bt     = (const int*)d_in[6];
    const int*   sl     = (const int*)d_in[7];
    float* out = (float*)d_out;

    float *q_ptr, *attn_ptr, *part_ptr;
    cudaGetSymbolAddress((void**)&q_ptr,    g_q);
    cudaGetSymbolAddress((void**)&attn_ptr, g_attn);
    cudaGetSymbolAddress((void**)&part_ptr, g_part);

    // Q projection only: reference never uses K/V columns of W_attn.
    gemm_part<<<dim3(32, 1, KS), 256>>>(hs, W_attn, part_ptr, 3 * HIDDEN);
    reduce_bias<<<128, 256>>>(part_ptr, b_attn, q_ptr);

    attn_kernel<<<dim3(NUM_SEQS, NUM_HEADS), 256>>>(kv, bt, sl);

    gemm_part<<<dim3(32, 1, KS), 256>>>(attn_ptr, W_proj, part_ptr, HIDDEN);
    reduce_bias<<<128, 256>>>(part_ptr, b_proj, out);
}

// round 5
// speedup vs baseline: 1.3663x; 1.0030x over previous
#include <cuda_runtime.h>

#define HIDDEN    2048
#define NUM_HEADS 16
#define HEAD_DIM  128
#define BLK_SZ    64
#define NUM_SEQS  64
#define MAX_BLK   32
#define KS        16
#define ATTN_SCALE 0.08838834764831845f   // 128^-0.5

// scratch (allocation-free __device__ globals), 16B-aligned for float4 access
__device__ __align__(16) float g_q[NUM_SEQS * HIDDEN];
__device__ __align__(16) float g_attn[NUM_SEQS * HIDDEN];
__device__ __align__(16) float g_part[KS * NUM_SEQS * HIDDEN];   // 8 MB

// ---------------------------------------------------------------------------
// Split-K tiled GEMM: C_part[z] = A[64, z*128:(z+1)*128] * B[..., n0:n0+64]
// BM=64, BN=64, BK=16, 8 K-tiles per CTA, double-buffered SMEM.
// grid = (32, 1, 16) = 512 CTAs (~3.5/SM), 256 threads, 4x4 micro-tile.
// ---------------------------------------------------------------------------
__global__ void gemm_part(const float* __restrict__ A, const float* __restrict__ B,
                          float* __restrict__ C, int ldb) {
    __shared__ __align__(16) float As[2][16 * 68];
    __shared__ __align__(16) float Bs[2][16 * 64];

    const int tid = threadIdx.x;
    const int tm  = tid >> 4;
    const int tn  = tid & 15;
    const int n0  = blockIdx.x * 64;
    const int z   = blockIdx.z;

    const int am  = tid >> 2;         // A row 0..63
    const int akq = (tid & 3) * 4;    // A k-offset {0,4,8,12}
    const int bk  = tid >> 4;         // B k 0..15
    const int bnq = (tid & 15) * 4;   // B n-offset

    const int kbase = z * 128;

    // prologue: stage 0
    {
        float4 a4 = *(const float4*)(A + (size_t)am * HIDDEN + kbase + akq);
        As[0][(akq + 0) * 68 + am] = a4.x;
        As[0][(akq + 1) * 68 + am] = a4.y;
        As[0][(akq + 2) * 68 + am] = a4.z;
        As[0][(akq + 3) * 68 + am] = a4.w;
        float4 b4 = *(const float4*)(B + (size_t)(kbase + bk) * ldb + n0 + bnq);
        *(float4*)(&Bs[0][bk * 64 + bnq]) = b4;
    }
    __syncthreads();

    float acc[4][4] = {};

#pragma unroll
    for (int it = 0; it < 8; ++it) {
        const int cur = it & 1;
        float4 a4, b4;
        if (it < 7) {
            const int k0 = kbase + (it + 1) * 16;
            a4 = *(const float4*)(A + (size_t)am * HIDDEN + k0 + akq);
            b4 = *(const float4*)(B + (size_t)(k0 + bk) * ldb + n0 + bnq);
        }
#pragma unroll
        for (int kk = 0; kk < 16; ++kk) {
            float4 av = *(const float4*)(&As[cur][kk * 68 + tm * 4]);
            float4 bv = *(const float4*)(&Bs[cur][kk * 64 + tn * 4]);
            float aa[4] = {av.x, av.y, av.z, av.w};
            float bb[4] = {bv.x, bv.y, bv.z, bv.w};
#pragma unroll
            for (int i = 0; i < 4; ++i)
#pragma unroll
                for (int j = 0; j < 4; ++j)
                    acc[i][j] += aa[i] * bb[j];
        }
        if (it < 7) {
            const int nxt = 1 - cur;
            As[nxt][(akq + 0) * 68 + am] = a4.x;
            As[nxt][(akq + 1) * 68 + am] = a4.y;
            As[nxt][(akq + 2) * 68 + am] = a4.z;
            As[nxt][(akq + 3) * 68 + am] = a4.w;
            *(float4*)(&Bs[nxt][bk * 64 + bnq]) = b4;
        }
        __syncthreads();
    }

#pragma unroll
    for (int i = 0; i < 4; ++i) {
        float4 v = make_float4(acc[i][0], acc[i][1], acc[i][2], acc[i][3]);
        *(float4*)(C + ((size_t)z * 64 + tm * 4 + i) * HIDDEN + n0 + tn * 4) = v;
    }
}

// out[i] = sum_z part[z][i] + bias[i % 2048]  (float4)
__global__ void reduce_bias(const float* __restrict__ part,
                            const float* __restrict__ bias,
                            float* __restrict__ out) {
    const int i = blockIdx.x * blockDim.x + threadIdx.x;   // 0..32767
    const float4* p = (const float4*)part;
    float4 r = ((const float4*)bias)[i & 511];
#pragma unroll
    for (int zz = 0; zz < KS; ++zz) {
        float4 a = p[i + zz * 32768];
        r.x += a.x; r.y += a.y; r.z += a.z; r.w += a.w;
    }
    ((float4*)out)[i] = r;
}

// ---------------------------------------------------------------------------
// Paged decode attention. grid = (64 seqs, 16 heads), 256 threads (8 warps).
// Token-per-quad layout: 4 lanes per token, 8 tokens per warp per round,
// 64 tokens (one KV block) per CTA round. MLP=8 loads/warp-iter, 2 shuffles
// reduce all 8 token dots at once.
// ---------------------------------------------------------------------------
__global__ void attn_kernel(const float* __restrict__ kv,
                            const int* __restrict__ bt,
                            const int* __restrict__ seq_lens) {
    const int s = blockIdx.x, h = blockIdx.y;
    const int tid = threadIdx.x;
    const int w  = tid >> 5;
    const int l  = tid & 31;
    const int q4 = l & 3;     // lane within quad (dim slice)
    const int qd = l >> 2;    // quad id -> token within warp's 8

    __shared__ __align__(16) float qs[HEAD_DIM];
    __shared__ __align__(16) float vacc[8][HEAD_DIM];
    __shared__ float sc[2048];
    __shared__ int   bts[MAX_BLK];
    __shared__ float red[8];
    __shared__ float bcast[2];

    if (tid < HEAD_DIM) qs[tid] = g_q[(size_t)s * HIDDEN + h * HEAD_DIM + tid];
    if (tid < MAX_BLK)  bts[tid] = bt[s * MAX_BLK + tid];
    const int sl = seq_lens[s];
    __syncthreads();

    // per-lane q slices: dims c*16 + q4*4 .. +4, c = 0..7
    float4 qreg[8];
#pragma unroll
    for (int c = 0; c < 8; ++c) qreg[c] = *(const float4*)(qs + c * 16 + q4 * 4);

    const int nblk = (sl + 63) >> 6;
    const int tok_in_blk = w * 8 + qd;           // 0..63
    const float* kbase = kv + (size_t)h * HEAD_DIM;

    // ---- pass 1: scores ----
    for (int blk = 0; blk < nblk; ++blk) {
        const int phys = bts[blk];
        const int t = blk * 64 + tok_in_blk;
        const float* kp = kbase + ((size_t)phys * BLK_SZ + tok_in_blk) * (size_t)HIDDEN;
        float d = 0.f;
#pragma unroll
        for (int c = 0; c < 8; ++c) {
            float4 kf = *(const float4*)(kp + c * 16 + q4 * 4);
            d += qreg[c].x * kf.x + qreg[c].y * kf.y + qreg[c].z * kf.z + qreg[c].w * kf.w;
        }
        d += __shfl_xor_sync(0xffffffffu, d, 1);
        d += __shfl_xor_sync(0xffffffffu, d, 2);
        if (q4 == 0 && t < sl) sc[t] = d * ATTN_SCALE;
    }
    __syncthreads();

    // ---- softmax: max ----
    float m = -3.4e38f;
    for (int t = tid; t < sl; t += 256) m = fmaxf(m, sc[t]);
#pragma unroll
    for (int o = 16; o; o >>= 1) m = fmaxf(m, __shfl_xor_sync(0xffffffffu, m, o));
    if (l == 0) red[w] = m;
    __syncthreads();
    if (tid == 0) {
        float mm = red[0];
#pragma unroll
        for (int i = 1; i < 8; ++i) mm = fmaxf(mm, red[i]);
        bcast[0] = mm;
    }
    __syncthreads();
    const float maxv = bcast[0];

    // ---- softmax: exp + sum ----
    float ssum = 0.f;
    for (int t = tid; t < sl; t += 256) {
        float e = __expf(sc[t] - maxv);
        sc[t] = e;
        ssum += e;
    }
#pragma unroll
    for (int o = 16; o; o >>= 1) ssum += __shfl_xor_sync(0xffffffffu, ssum, o);
    if (l == 0) red[w] = ssum;
    __syncthreads();
    if (tid == 0) {
        float t2 = 0.f;
#pragma unroll
        for (int i = 0; i < 8; ++i) t2 += red[i];
        bcast[1] = 1.f / t2;
    }
    __syncthreads();

    // ---- pass 2: weighted V ----
    const float* vbase = kv + (size_t)2048 * 64 * 16 * 128 + (size_t)h * HEAD_DIM;
    float4 acc[8];
#pragma unroll
    for (int c = 0; c < 8; ++c) acc[c] = make_float4(0.f, 0.f, 0.f, 0.f);

    for (int blk = 0; blk < nblk; ++blk) {
        const int phys = bts[blk];
        const int t = blk * 64 + tok_in_blk;
        const float wt = (t < sl) ? sc[t] : 0.f;
        const float* vp = vbase + ((size_t)phys * BLK_SZ + tok_in_blk) * (size_t)HIDDEN;
#pragma unroll
        for (int c = 0; c < 8; ++c) {
            float4 vf = *(const float4*)(vp + c * 16 + q4 * 4);
            acc[c].x += wt * vf.x;
            acc[c].y += wt * vf.y;
            acc[c].z += wt * vf.z;
            acc[c].w += wt * vf.w;
        }
    }

    // cross-quad reduction (quads hold different token subsets, same dims)
#pragma unroll
    for (int off = 4; off <= 16; off <<= 1) {
#pragma unroll
        for (int c = 0; c < 8; ++c) {
            acc[c].x += __shfl_xor_sync(0xffffffffu, acc[c].x, off);
            acc[c].y += __shfl_xor_sync(0xffffffffu, acc[c].y, off);
            acc[c].z += __shfl_xor_sync(0xffffffffu, acc[c].z, off);
            acc[c].w += __shfl_xor_sync(0xffffffffu, acc[c].w, off);
        }
    }
    if (qd == 0) {
#pragma unroll
        for (int c = 0; c < 8; ++c)
            *(float4*)(&vacc[w][c * 16 + q4 * 4]) = acc[c];
    }
    __syncthreads();

    if (tid < HEAD_DIM) {
        float r = 0.f;
#pragma unroll
        for (int ww = 0; ww < 8; ++ww) r += vacc[ww][tid];
        g_attn[(size_t)s * HIDDEN + h * HEAD_DIM + tid] = r * bcast[1];
    }
}

// ---------------------------------------------------------------------------
extern "C" void kernel_launch(void* const* d_in, const int* in_sizes, int n_in,
                              void* d_out, int out_size) {
    const float* hs     = (const float*)d_in[0];
    const float* kv     = (const float*)d_in[1];
    const float* W_attn = (const float*)d_in[2];
    const float* b_attn = (const float*)d_in[3];
    const float* W_proj = (const float*)d_in[4];
    const float* b_proj = (const float*)d_in[5];
    const int*   bt     = (const int*)d_in[6];
    const int*   sl     = (const int*)d_in[7];
    float* out = (float*)d_out;

    float *q_ptr, *attn_ptr, *part_ptr;
    cudaGetSymbolAddress((void**)&q_ptr,    g_q);
    cudaGetSymbolAddress((void**)&attn_ptr, g_attn);
    cudaGetSymbolAddress((void**)&part_ptr, g_part);

    // Q projection only: reference never uses K/V columns of W_attn.
    gemm_part<<<dim3(32, 1, KS), 256>>>(hs, W_attn, part_ptr, 3 * HIDDEN);
    reduce_bias<<<128, 256>>>(part_ptr, b_attn, q_ptr);

    attn_kernel<<<dim3(NUM_SEQS, NUM_HEADS), 256>>>(kv, bt, sl);

    gemm_part<<<dim3(32, 1, KS), 256>>>(attn_ptr, W_proj, part_ptr, HIDDEN);
    reduce_bias<<<128, 256>>>(part_ptr, b_proj, out);
}

// round 7
// speedup vs baseline: 1.5069x; 1.1029x over previous
#include <cuda_runtime.h>

#define HIDDEN    2048
#define NUM_HEADS 16
#define HEAD_DIM  128
#define BLK_SZ    64
#define NUM_SEQS  64
#define MAX_BLK   32
#define KS        16
#define NSPLIT    4
#define CHUNK     512              // tokens per split chunk (8 KV blocks)
#define ATTN_SCALE 0.08838834764831845f   // 128^-0.5

// scratch (allocation-free __device__ globals), 16B-aligned for float4 access
__device__ __align__(16) float g_q[NUM_SEQS * HIDDEN];
__device__ __align__(16) float g_attn[NUM_SEQS * HIDDEN];
__device__ __align__(16) float g_part[KS * NUM_SEQS * HIDDEN];   // 8 MB
// flash-decode partials
__device__ __align__(16) float g_po[NUM_SEQS * NUM_HEADS * NSPLIT * HEAD_DIM];
__device__ float g_pm[NUM_SEQS * NUM_HEADS * NSPLIT];
__device__ float g_pl[NUM_SEQS * NUM_HEADS * NSPLIT];

// ---------------------------------------------------------------------------
// Split-K tiled GEMM (unchanged from R5): grid=(32,1,16), 256 thr, 4x4 tile.
// ---------------------------------------------------------------------------
__global__ void gemm_part(const float* __restrict__ A, const float* __restrict__ B,
                          float* __restrict__ C, int ldb) {
    __shared__ __align__(16) float As[2][16 * 68];
    __shared__ __align__(16) float Bs[2][16 * 64];

    const int tid = threadIdx.x;
    const int tm  = tid >> 4;
    const int tn  = tid & 15;
    const int n0  = blockIdx.x * 64;
    const int z   = blockIdx.z;

    const int am  = tid >> 2;
    const int akq = (tid & 3) * 4;
    const int bk  = tid >> 4;
    const int bnq = (tid & 15) * 4;

    const int kbase = z * 128;

    {
        float4 a4 = *(const float4*)(A + (size_t)am * HIDDEN + kbase + akq);
        As[0][(akq + 0) * 68 + am] = a4.x;
        As[0][(akq + 1) * 68 + am] = a4.y;
        As[0][(akq + 2) * 68 + am] = a4.z;
        As[0][(akq + 3) * 68 + am] = a4.w;
        float4 b4 = *(const float4*)(B + (size_t)(kbase + bk) * ldb + n0 + bnq);
        *(float4*)(&Bs[0][bk * 64 + bnq]) = b4;
    }
    __syncthreads();

    float acc[4][4] = {};

#pragma unroll
    for (int it = 0; it < 8; ++it) {
        const int cur = it & 1;
        float4 a4, b4;
        if (it < 7) {
            const int k0 = kbase + (it + 1) * 16;
            a4 = *(const float4*)(A + (size_t)am * HIDDEN + k0 + akq);
            b4 = *(const float4*)(B + (size_t)(k0 + bk) * ldb + n0 + bnq);
        }
#pragma unroll
        for (int kk = 0; kk < 16; ++kk) {
            float4 av = *(const float4*)(&As[cur][kk * 68 + tm * 4]);
            float4 bv = *(const float4*)(&Bs[cur][kk * 64 + tn * 4]);
            float aa[4] = {av.x, av.y, av.z, av.w};
            float bb[4] = {bv.x, bv.y, bv.z, bv.w};
#pragma unroll
            for (int i = 0; i < 4; ++i)
#pragma unroll
                for (int j = 0; j < 4; ++j)
                    acc[i][j] += aa[i] * bb[j];
        }
        if (it < 7) {
            const int nxt = 1 - cur;
            As[nxt][(akq + 0) * 68 + am] = a4.x;
            As[nxt][(akq + 1) * 68 + am] = a4.y;
            As[nxt][(akq + 2) * 68 + am] = a4.z;
            As[nxt][(akq + 3) * 68 + am] = a4.w;
            *(float4*)(&Bs[nxt][bk * 64 + bnq]) = b4;
        }
        __syncthreads();
    }

#pragma unroll
    for (int i = 0; i < 4; ++i) {
        float4 v = make_float4(acc[i][0], acc[i][1], acc[i][2], acc[i][3]);
        *(float4*)(C + ((size_t)z * 64 + tm * 4 + i) * HIDDEN + n0 + tn * 4) = v;
    }
}

// out[i] = sum_z part[z][i] + bias[i % 2048]  (float4)
__global__ void reduce_bias(const float* __restrict__ part,
                            const float* __restrict__ bias,
                            float* __restrict__ out) {
    const int i = blockIdx.x * blockDim.x + threadIdx.x;
    const float4* p = (const float4*)part;
    float4 r = ((const float4*)bias)[i & 511];
#pragma unroll
    for (int zz = 0; zz < KS; ++zz) {
        float4 a = p[i + zz * 32768];
        r.x += a.x; r.y += a.y; r.z += a.z; r.w += a.w;
    }
    ((float4*)out)[i] = r;
}

// ---------------------------------------------------------------------------
// Flash-decode split attention: grid = (64 seqs, 16 heads, 4 chunks), 256 thr.
// Each CTA handles <=512 tokens of one (seq, head): partial softmax
// (m, l, unnormalized o) written to g_pm/g_pl/g_po.
// ---------------------------------------------------------------------------
__global__ void attn_split(const float* __restrict__ kv,
                           const int* __restrict__ bt,
                           const int* __restrict__ seq_lens) {
    const int s = blockIdx.x, h = blockIdx.y, z = blockIdx.z;
    const int sl = seq_lens[s];
    const int start = z * CHUNK;
    if (start >= sl) return;                       // inactive chunk
    const int clen = min(sl - start, CHUNK);       // tokens in this chunk

    const int tid = threadIdx.x;
    const int w  = tid >> 5;
    const int l  = tid & 31;
    const int q4 = l & 3;     // dim slice within quad
    const int qd = l >> 2;    // token within warp's 8

    __shared__ __align__(16) float qs[HEAD_DIM];
    __shared__ __align__(16) float vacc[8][HEAD_DIM];
    __shared__ float sc[CHUNK];
    __shared__ int   bts[8];
    __shared__ float red[8];
    __shared__ float bcast[2];

    if (tid < HEAD_DIM) qs[tid] = g_q[(size_t)s * HIDDEN + h * HEAD_DIM + tid];
    const int nblk = (clen + 63) >> 6;             // KV blocks in chunk (<=8)
    if (tid < nblk) bts[tid] = bt[s * MAX_BLK + z * 8 + tid];
    __syncthreads();

    float4 qreg[8];
#pragma unroll
    for (int c = 0; c < 8; ++c) qreg[c] = *(const float4*)(qs + c * 16 + q4 * 4);

    const int tok_in_blk = w * 8 + qd;             // 0..63
    const float* kbase = kv + (size_t)h * HEAD_DIM;

    // ---- pass 1: scores ----
    for (int blk = 0; blk < nblk; ++blk) {
        const int phys = bts[blk];
        const int tl = blk * 64 + tok_in_blk;      // local token idx in chunk
        const float* kp = kbase + ((size_t)phys * BLK_SZ + tok_in_blk) * (size_t)HIDDEN;
        float d = 0.f;
#pragma unroll
        for (int c = 0; c < 8; ++c) {
            float4 kf = *(const float4*)(kp + c * 16 + q4 * 4);
            d += qreg[c].x * kf.x + qreg[c].y * kf.y + qreg[c].z * kf.z + qreg[c].w * kf.w;
        }
        d += __shfl_xor_sync(0xffffffffu, d, 1);
        d += __shfl_xor_sync(0xffffffffu, d, 2);
        if (q4 == 0 && tl < clen) sc[tl] = d * ATTN_SCALE;
    }
    __syncthreads();

    // ---- chunk max ----
    float m = -3.4e38f;
    for (int t = tid; t < clen; t += 256) m = fmaxf(m, sc[t]);
#pragma unroll
    for (int o = 16; o; o >>= 1) m = fmaxf(m, __shfl_xor_sync(0xffffffffu, m, o));
    if (l == 0) red[w] = m;
    __syncthreads();
    if (tid == 0) {
        float mm = red[0];
#pragma unroll
        for (int i = 1; i < 8; ++i) mm = fmaxf(mm, red[i]);
        bcast[0] = mm;
    }
    __syncthreads();
    const float maxv = bcast[0];

    // ---- exp + sum ----
    float ssum = 0.f;
    for (int t = tid; t < clen; t += 256) {
        float e = __expf(sc[t] - maxv);
        sc[t] = e;
        ssum += e;
    }
#pragma unroll
    for (int o = 16; o; o >>= 1) ssum += __shfl_xor_sync(0xffffffffu, ssum, o);
    if (l == 0) red[w] = ssum;
    __syncthreads();
    if (tid == 0) {
        float t2 = 0.f;
#pragma unroll
        for (int i = 0; i < 8; ++i) t2 += red[i];
        bcast[1] = t2;
    }

    // ---- pass 2: weighted V (unnormalized) ----
    const float* vbase = kv + (size_t)2048 * 64 * 16 * 128 + (size_t)h * HEAD_DIM;
    float4 acc[8];
#pragma unroll
    for (int c = 0; c < 8; ++c) acc[c] = make_float4(0.f, 0.f, 0.f, 0.f);

    for (int blk = 0; blk < nblk; ++blk) {
        const int phys = bts[blk];
        const int tl = blk * 64 + tok_in_blk;
        const float wt = (tl < clen) ? sc[tl] : 0.f;
        const float* vp = vbase + ((size_t)phys * BLK_SZ + tok_in_blk) * (size_t)HIDDEN;
#pragma unroll
        for (int c = 0; c < 8; ++c) {
            float4 vf = *(const float4*)(vp + c * 16 + q4 * 4);
            acc[c].x += wt * vf.x;
            acc[c].y += wt * vf.y;
            acc[c].z += wt * vf.z;
            acc[c].w += wt * vf.w;
        }
    }

#pragma unroll
    for (int off = 4; off <= 16; off <<= 1) {
#pragma unroll
        for (int c = 0; c < 8; ++c) {
            acc[c].x += __shfl_xor_sync(0xffffffffu, acc[c].x, off);
            acc[c].y += __shfl_xor_sync(0xffffffffu, acc[c].y, off);
            acc[c].z += __shfl_xor_sync(0xffffffffu, acc[c].z, off);
            acc[c].w += __shfl_xor_sync(0xffffffffu, acc[c].w, off);
        }
    }
    if (qd == 0) {
#pragma unroll
        for (int c = 0; c < 8; ++c)
            *(float4*)(&vacc[w][c * 16 + q4 * 4]) = acc[c];
    }
    __syncthreads();

    const int pidx = (s * NUM_HEADS + h) * NSPLIT + z;
    if (tid < HEAD_DIM) {
        float r = 0.f;
#pragma unroll
        for (int ww = 0; ww < 8; ++ww) r += vacc[ww][tid];
        g_po[(size_t)pidx * HEAD_DIM + tid] = r;
    }
    if (tid == 0) { g_pm[pidx] = maxv; g_pl[pidx] = bcast[1]; }
}

// combine partials: grid (64,16), 128 threads
__global__ void attn_combine(const int* __restrict__ seq_lens) {
    const int s = blockIdx.x, h = blockIdx.y;
    const int d = threadIdx.x;
    const int sl = seq_lens[s];
    const int nch = (sl + CHUNK - 1) / CHUNK;
    const int pbase = (s * NUM_HEADS + h) * NSPLIT;

    float M = -3.4e38f;
    for (int zz = 0; zz < nch; ++zz) M = fmaxf(M, g_pm[pbase + zz]);
    float L = 0.f, o = 0.f;
    for (int zz = 0; zz < nch; ++zz) {
        const float f = __expf(g_pm[pbase + zz] - M);
        L += g_pl[pbase + zz] * f;
        o += g_po[(size_t)(pbase + zz) * HEAD_DIM + d] * f;
    }
    g_attn[(size_t)s * HIDDEN + h * HEAD_DIM + d] = o / L;
}

// ---------------------------------------------------------------------------
extern "C" void kernel_launch(void* const* d_in, const int* in_sizes, int n_in,
                              void* d_out, int out_size) {
    const float* hs     = (const float*)d_in[0];
    const float* kv     = (const float*)d_in[1];
    const float* W_attn = (const float*)d_in[2];
    const float* b_attn = (const float*)d_in[3];
    const float* W_proj = (const float*)d_in[4];
    const float* b_proj = (const float*)d_in[5];
    const int*   bt     = (const int*)d_in[6];
    const int*   sl     = (const int*)d_in[7];
    float* out = (float*)d_out;

    float *q_ptr, *attn_ptr, *part_ptr;
    cudaGetSymbolAddress((void**)&q_ptr,    g_q);
    cudaGetSymbolAddress((void**)&attn_ptr, g_attn);
    cudaGetSymbolAddress((void**)&part_ptr, g_part);

    // Q projection only: reference never uses K/V columns of W_attn.
    gemm_part<<<dim3(32, 1, KS), 256>>>(hs, W_attn, part_ptr, 3 * HIDDEN);
    reduce_bias<<<128, 256>>>(part_ptr, b_attn, q_ptr);

    attn_split<<<dim3(NUM_SEQS, NUM_HEADS, NSPLIT), 256>>>(kv, bt, sl);
    attn_combine<<<dim3(NUM_SEQS, NUM_HEADS), 128>>>(sl);

    gemm_part<<<dim3(32, 1, KS), 256>>>(attn_ptr, W_proj, part_ptr, HIDDEN);
    reduce_bias<<<128, 256>>>(part_ptr, b_proj, out);
}